// round 4
// baseline (speedup 1.0000x reference)
#include <cuda_runtime.h>
#include <cstdint>

#define Hh   768
#define Tt   512
#define BSs  32
#define G3   2304
#define NCTA 96
#define NTHR 128

// ---------------- device scratch (static, no allocation) ----------------
__device__ __align__(16) static float g_xg[(size_t)BSs * Tt * G3];      // 151 MB
__device__ __align__(16) static unsigned long long g_hb[2][Hh];        // tagged h double buffer
__device__ static int g_L[BSs];
__device__ static int g_mask64;   // 1 if mask buffer is int64-packed, else 0

// ---------------- helpers ----------------
__device__ __forceinline__ void fma2(unsigned long long& acc,
                                     unsigned long long a,
                                     unsigned long long b) {
    asm("fma.rn.f32x2 %0, %1, %2, %0;" : "+l"(acc) : "l"(a), "l"(b));
}

__device__ __forceinline__ void ldcv2(const unsigned long long* p,
                                      unsigned long long& a,
                                      unsigned long long& b) {
    asm volatile("ld.global.cv.v2.u64 {%0,%1},[%2];"
                 : "=l"(a), "=l"(b) : "l"(p));
}

__device__ __forceinline__ float sigf(float x) {
    return __fdividef(1.0f, 1.0f + __expf(-x));
}
__device__ __forceinline__ float tanh_fast(float x) {
    return __fdividef(2.0f, 1.0f + __expf(-2.0f * x)) - 1.0f;
}

// ---------------- kernel 0: detect mask element width ----------------
// If the mask is truly int64 with values {0,1}, every odd 32-bit word of the
// first BSs*Tt words is zero. For int32 masks ~half the odd words are 1.
__global__ void k_detect(const int* __restrict__ m32) {
    __shared__ int any;
    if (threadIdx.x == 0) any = 0;
    __syncthreads();
    int local = 0;
    for (int i = threadIdx.x; i < (BSs * Tt) / 2; i += 1024)
        local |= (m32[2 * i + 1] != 0);
    if (local) atomicOr(&any, 1);
    __syncthreads();
    if (threadIdx.x == 0) g_mask64 = (any == 0) ? 1 : 0;
}

// ---------------- kernel 1: sequence lengths ----------------
__global__ void k_len(const int* __restrict__ m32) {
    int b = blockIdx.x;
    int w64 = g_mask64;
    int c = 0;
    for (int i = threadIdx.x; i < Tt; i += 256) {
        int idx = b * Tt + i;
        int v = w64 ? m32[2 * idx] : m32[idx];   // low word carries the value
        c += (v == 0) ? 1 : 0;
    }
    for (int o = 16; o; o >>= 1) c += __shfl_xor_sync(0xFFFFFFFFu, c, o);
    __shared__ int sc[8];
    if ((threadIdx.x & 31) == 0) sc[threadIdx.x >> 5] = c;
    __syncthreads();
    if (threadIdx.x == 0) {
        int tot = 0;
#pragma unroll
        for (int w = 0; w < 8; w++) tot += sc[w];
        int L = Tt - tot;
        if (L < 1) L = 2;
        g_L[b] = L;
    }
}

// ---------------- kernel 2: init tagged h buffers ----------------
__global__ void k_init(const float* __restrict__ gc) {
    int j = blockIdx.x * 256 + threadIdx.x;
    if (j < Hh) {
        g_hb[0][j] = (unsigned long long)__float_as_uint(gc[j]);   // tag 0 in high bits
        g_hb[1][j] = 0xFFFFFFFF00000000ull;                        // invalid tag
    }
}

// ---------------- kernel 3: xg = emb @ W_ih^T + b_ih (skip masked tiles) ----------------
#define BM 64
#define BN 64
#define BK 16
__global__ void __launch_bounds__(256)
k_gemm(const float* __restrict__ A, const float* __restrict__ B,
       const float* __restrict__ bih) {
    int mt = blockIdx.y, nt = blockIdx.x;
    int b = mt >> 3;
    int t0 = (mt & 7) * BM;
    if (t0 >= g_L[b]) return;   // whole tile beyond this sample's length

    __shared__ float As[BK][BM + 4];
    __shared__ float Bs[BK][BN + 4];

    int tid = threadIdx.x;
    int tx = tid & 15, ty = tid >> 4;
    int lr = tid >> 2, lk = (tid & 3) * 4;

    const float* Ab = A + (size_t)(mt * BM) * Hh;
    const float* Bb = B + (size_t)(nt * BN) * Hh;

    float c[4][4] = {};

    for (int k0 = 0; k0 < Hh; k0 += BK) {
        float4 av = *(const float4*)&Ab[(size_t)lr * Hh + k0 + lk];
        float4 bv = *(const float4*)&Bb[(size_t)lr * Hh + k0 + lk];
        As[lk + 0][lr] = av.x; As[lk + 1][lr] = av.y;
        As[lk + 2][lr] = av.z; As[lk + 3][lr] = av.w;
        Bs[lk + 0][lr] = bv.x; Bs[lk + 1][lr] = bv.y;
        Bs[lk + 2][lr] = bv.z; Bs[lk + 3][lr] = bv.w;
        __syncthreads();
#pragma unroll
        for (int kk = 0; kk < BK; kk++) {
            float4 a4 = *(const float4*)&As[kk][ty * 4];
            float4 b4 = *(const float4*)&Bs[kk][tx * 4];
            float ar[4] = {a4.x, a4.y, a4.z, a4.w};
            float br[4] = {b4.x, b4.y, b4.z, b4.w};
#pragma unroll
            for (int i = 0; i < 4; i++)
#pragma unroll
                for (int j = 0; j < 4; j++)
                    c[i][j] = fmaf(ar[i], br[j], c[i][j]);
        }
        __syncthreads();
    }

    float4 bias = *(const float4*)&bih[nt * BN + tx * 4];
#pragma unroll
    for (int i = 0; i < 4; i++) {
        size_t m = (size_t)(mt * BM + ty * 4 + i);
        float4 o;
        o.x = c[i][0] + bias.x;
        o.y = c[i][1] + bias.y;
        o.z = c[i][2] + bias.z;
        o.w = c[i][3] + bias.w;
        *(float4*)&g_xg[m * G3 + nt * BN + tx * 4] = o;
    }
}

// ---------------- kernel 4: serial GRU recurrence (dataflow, tagged 8B words) ----------------
__global__ void __launch_bounds__(NTHR, 1)
k_rnn(const float* __restrict__ gc, const float* __restrict__ Whh,
      const float* __restrict__ bhh, float* __restrict__ out, int out_size) {
    int tid  = threadIdx.x;
    int lane = tid & 31;
    int warp = tid >> 5;          // 0..3
    int cta  = blockIdx.x;        // 0..95

    __shared__ __align__(16) float hs[Hh];
    __shared__ int sL[BSs];
    if (tid < BSs) sL[tid] = g_L[tid];

    int e   = lane & 1;                          // which of this warp's 2 elements I finalize
    int j_e = cta * 8 + warp * 2 + e;            // my h element (for lanes 0/1)

    // --- stationary W_hh slice in registers: [elem][gate][k] packed f32x2 ---
    unsigned long long w[2][3][12];
#pragma unroll
    for (int ee = 0; ee < 2; ee++) {
        int j = cta * 8 + warp * 2 + ee;
#pragma unroll
        for (int g = 0; g < 3; g++) {
            const float* wr = Whh + (size_t)(g * Hh + j) * Hh + 2 * lane;
#pragma unroll
            for (int k = 0; k < 12; k++)
                w[ee][g][k] = *(const unsigned long long*)(wr + 64 * k);
        }
    }

    float bh0 = __ldg(&bhh[j_e]);
    float bh1 = __ldg(&bhh[Hh + j_e]);
    float bh2 = __ldg(&bhh[2 * Hh + j_e]);
    float h_cur = __ldg(&gc[j_e]);

    __syncthreads();

    int pbase = tid * 6;   // 6 tagged elements polled by this thread
    int s = 0;             // global serial step counter (== tag)

    for (int b = 0; b < BSs; b++) {
        int Lb = sL[b];
        const float* xgb = g_xg + (size_t)b * Tt * G3;
        for (int t = 0; t < Lb; t++) {
            // prefetch this step's xg for my element (overlaps the poll)
            float xr = 0.f, xz = 0.f, xn = 0.f;
            if (lane < 2) {
                const float* x = xgb + (size_t)t * G3 + j_e;
                xr = __ldg(x);
                xz = __ldg(x + Hh);
                xn = __ldg(x + 2 * Hh);
            }

            // ---- poll tagged h words (sync + data in one 8B L2 round trip) ----
            const unsigned long long* hb = g_hb[s & 1];
            unsigned int tg = (unsigned int)s;
            bool d0 = false, d1 = false, d2 = false;
            while (!(d0 && d1 && d2)) {
                unsigned long long va, vb;
                if (!d0) {
                    ldcv2(hb + pbase, va, vb);
                    if ((unsigned int)(va >> 32) == tg && (unsigned int)(vb >> 32) == tg) {
                        hs[pbase]     = __uint_as_float((unsigned int)va);
                        hs[pbase + 1] = __uint_as_float((unsigned int)vb);
                        d0 = true;
                    }
                }
                if (!d1) {
                    ldcv2(hb + pbase + 2, va, vb);
                    if ((unsigned int)(va >> 32) == tg && (unsigned int)(vb >> 32) == tg) {
                        hs[pbase + 2] = __uint_as_float((unsigned int)va);
                        hs[pbase + 3] = __uint_as_float((unsigned int)vb);
                        d1 = true;
                    }
                }
                if (!d2) {
                    ldcv2(hb + pbase + 4, va, vb);
                    if ((unsigned int)(va >> 32) == tg && (unsigned int)(vb >> 32) == tg) {
                        hs[pbase + 4] = __uint_as_float((unsigned int)va);
                        hs[pbase + 5] = __uint_as_float((unsigned int)vb);
                        d2 = true;
                    }
                }
            }
            __syncthreads();

            // ---- 6 dot products (f32x2 FMAs, W stationary in registers) ----
            unsigned long long acc[2][3];
#pragma unroll
            for (int ee = 0; ee < 2; ee++)
#pragma unroll
                for (int g = 0; g < 3; g++) acc[ee][g] = 0ull;

            const unsigned long long* hp = (const unsigned long long*)hs + lane;
#pragma unroll
            for (int k = 0; k < 12; k++) {
                unsigned long long hv = hp[32 * k];
#pragma unroll
                for (int ee = 0; ee < 2; ee++)
#pragma unroll
                    for (int g = 0; g < 3; g++) fma2(acc[ee][g], w[ee][g][k], hv);
            }

            float sum[2][3];
#pragma unroll
            for (int ee = 0; ee < 2; ee++)
#pragma unroll
                for (int g = 0; g < 3; g++) {
                    unsigned long long a = acc[ee][g];
                    float x = __uint_as_float((unsigned int)a) +
                              __uint_as_float((unsigned int)(a >> 32));
#pragma unroll
                    for (int o = 16; o; o >>= 1)
                        x += __shfl_xor_sync(0xFFFFFFFFu, x, o);
                    sum[ee][g] = x;
                }

            // ---- gates + publish h_new (lanes 0 and 1 each own one element) ----
            float hg_r = (e ? sum[1][0] : sum[0][0]) + bh0;
            float hg_z = (e ? sum[1][1] : sum[0][1]) + bh1;
            float hg_n = (e ? sum[1][2] : sum[0][2]) + bh2;
            if (lane < 2) {
                float r  = sigf(xr + hg_r);
                float z  = sigf(xz + hg_z);
                float n  = tanh_fast(xn + r * hg_n);
                float hn = (1.0f - z) * n + z * h_cur;
                h_cur = hn;
                unsigned long long pv =
                    ((unsigned long long)(unsigned int)(s + 1) << 32) |
                    (unsigned long long)__float_as_uint(hn);
                __stcg(&g_hb[(s + 1) & 1][j_e], pv);
            }
            s++;
            __syncthreads();   // protect hs before next poll overwrites it
        }
        if (lane < 2) out[b * Hh + j_e] = h_cur;   // per-sample final hidden state
    }
    if (lane < 2 && out_size >= BSs * Hh + Hh)
        out[BSs * Hh + j_e] = h_cur;               // detached final context hF
}

// ---------------- launch ----------------
extern "C" void kernel_launch(void* const* d_in, const int* in_sizes, int n_in,
                              void* d_out, int out_size) {
    const float* emb  = (const float*)d_in[0];
    const int*   mask = (const int*)d_in[1];      // int64 in source -> int32 under JAX default
    const float* gc   = (const float*)d_in[2];
    const float* Wih  = (const float*)d_in[3];
    const float* Whh  = (const float*)d_in[4];
    const float* bih  = (const float*)d_in[5];
    const float* bhh  = (const float*)d_in[6];
    float* out = (float*)d_out;

    k_detect<<<1, 1024>>>(mask);
    k_len<<<BSs, 256>>>(mask);
    k_init<<<3, 256>>>(gc);
    dim3 gg(G3 / BN, (BSs * Tt) / BM);
    k_gemm<<<gg, 256>>>(emb, Wih, bih);
    k_rnn<<<NCTA, NTHR>>>(gc, Whh, bhh, out, out_size);
}

// round 5
// speedup vs baseline: 1.0190x; 1.0190x over previous
#include <cuda_runtime.h>
#include <cstdint>

#define Hh   768
#define Tt   512
#define BSs  32
#define G3   2304
#define NCTA 96
#define NTHR 128

typedef unsigned long long ull;

// ---------------- device scratch (static, no allocation) ----------------
__device__ __align__(16) static float g_xg[(size_t)BSs * Tt * G3];   // 151 MB
__device__ __align__(16) static ull g_hb[2][Hh];                     // tagged h double buffer
__device__ static int g_L[BSs];

// ---------------- helpers ----------------
__device__ __forceinline__ void fma2(ull& acc, ull a, ull b) {
    asm("fma.rn.f32x2 %0, %1, %2, %0;" : "+l"(acc) : "l"(a), "l"(b));
}
__device__ __forceinline__ ull pack2(float x) {
    ull r; asm("mov.b64 %0, {%1, %1};" : "=l"(r) : "f"(x)); return r;
}
__device__ __forceinline__ void unpack2(ull v, float& lo, float& hi) {
    asm("mov.b64 {%0, %1}, %2;" : "=f"(lo), "=f"(hi) : "l"(v));
}
__device__ __forceinline__ void ldcv2(const ull* p, ull& a, ull& b) {
    asm volatile("ld.global.cv.v2.u64 {%0,%1},[%2];" : "=l"(a), "=l"(b) : "l"(p));
}
__device__ __forceinline__ float sigf(float x) {
    return __fdividef(1.0f, 1.0f + __expf(-x));
}
__device__ __forceinline__ float tanh_fast(float x) {
    return __fdividef(2.0f, 1.0f + __expf(-2.0f * x)) - 1.0f;
}

// ---------------- kernel 1: prep = mask-width detect + lengths + h-buffer init ----------------
// blocks 0..31: per-sample length; block 32: init tagged h buffers.
// Width detect per block: if mask buffer were int64 {0,1}, all odd 32-bit words of
// the first 16384 words are zero (safe region under either layout).
__global__ void k_prep(const int* __restrict__ m32, const float* __restrict__ gc) {
    int blk = blockIdx.x;
    if (blk == BSs) {
        for (int j = threadIdx.x; j < Hh; j += 256) {
            g_hb[0][j] = (ull)__float_as_uint(gc[j]);   // tag 0 in high bits
            g_hb[1][j] = 0xFFFFFFFF00000000ull;         // invalid tag
        }
        return;
    }
    __shared__ int s_any;
    if (threadIdx.x == 0) s_any = 0;
    __syncthreads();
    int local = 0;
    for (int i = threadIdx.x; i < (BSs * Tt) / 2; i += 256)
        local |= (m32[2 * i + 1] != 0);
    if (local) atomicOr(&s_any, 1);
    __syncthreads();
    int w64 = (s_any == 0);   // all odd words zero -> int64-packed

    int b = blk;
    int c = 0;
    for (int i = threadIdx.x; i < Tt; i += 256) {
        int idx = b * Tt + i;
        int v = w64 ? m32[2 * idx] : m32[idx];
        c += (v == 0) ? 1 : 0;
    }
    for (int o = 16; o; o >>= 1) c += __shfl_xor_sync(0xFFFFFFFFu, c, o);
    __shared__ int sc[8];
    if ((threadIdx.x & 31) == 0) sc[threadIdx.x >> 5] = c;
    __syncthreads();
    if (threadIdx.x == 0) {
        int tot = 0;
#pragma unroll
        for (int w = 0; w < 8; w++) tot += sc[w];
        int L = Tt - tot;
        if (L < 1) L = 2;
        g_L[b] = L;
    }
}

// ---------------- kernel 2: xg = emb @ W_ih^T + b_ih (128x128x8, f32x2, skip masked tiles) ----------------
#define GM 128
#define GN 128
#define GK 8
__global__ void __launch_bounds__(256)
k_gemm(const float* __restrict__ A, const float* __restrict__ B,
       const float* __restrict__ bih) {
    int mt = blockIdx.y, nt = blockIdx.x;
    int b = mt >> 2;
    int t0 = (mt & 3) * GM;
    if (t0 >= g_L[b]) return;   // whole 128-row tile beyond this sample's length

    __shared__ __align__(16) float As[GK][GM + 4];
    __shared__ __align__(16) float Bs[GK][GN + 4];

    int tid = threadIdx.x;
    int lr = tid >> 1;          // 0..127: row loaded by this thread
    int lk = (tid & 1) * 4;     // 0 or 4: k-offset
    int tx = tid & 15;          // micro-tile col group (8 cols)
    int ty = tid >> 4;          // micro-tile row group (8 rows)

    const float* Ab = A + (size_t)(mt * GM) * Hh;
    const float* Bb = B + (size_t)(nt * GN) * Hh;

    ull c2[8][4];
#pragma unroll
    for (int i = 0; i < 8; i++)
#pragma unroll
        for (int j = 0; j < 4; j++) c2[i][j] = 0ull;

    for (int k0 = 0; k0 < Hh; k0 += GK) {
        float4 av = *(const float4*)&Ab[(size_t)lr * Hh + k0 + lk];
        float4 bv = *(const float4*)&Bb[(size_t)lr * Hh + k0 + lk];
        As[lk + 0][lr] = av.x; As[lk + 1][lr] = av.y;
        As[lk + 2][lr] = av.z; As[lk + 3][lr] = av.w;
        Bs[lk + 0][lr] = bv.x; Bs[lk + 1][lr] = bv.y;
        Bs[lk + 2][lr] = bv.z; Bs[lk + 3][lr] = bv.w;
        __syncthreads();
#pragma unroll
        for (int kk = 0; kk < GK; kk++) {
            float4 a0 = *(const float4*)&As[kk][ty * 8];
            float4 a1 = *(const float4*)&As[kk][ty * 8 + 4];
            const ull* bp = (const ull*)&Bs[kk][tx * 8];
            ull b2[4] = {bp[0], bp[1], bp[2], bp[3]};
            float ar[8] = {a0.x, a0.y, a0.z, a0.w, a1.x, a1.y, a1.z, a1.w};
#pragma unroll
            for (int i = 0; i < 8; i++) {
                ull ap = pack2(ar[i]);
#pragma unroll
                for (int j = 0; j < 4; j++) fma2(c2[i][j], ap, b2[j]);
            }
        }
        __syncthreads();
    }

    float4 bias0 = *(const float4*)&bih[nt * GN + tx * 8];
    float4 bias1 = *(const float4*)&bih[nt * GN + tx * 8 + 4];
    float bsc[8] = {bias0.x, bias0.y, bias0.z, bias0.w,
                    bias1.x, bias1.y, bias1.z, bias1.w};
#pragma unroll
    for (int i = 0; i < 8; i++) {
        size_t m = (size_t)(mt * GM + ty * 8 + i);
        float o[8];
#pragma unroll
        for (int j = 0; j < 4; j++) unpack2(c2[i][j], o[2 * j], o[2 * j + 1]);
        float4 w0, w1;
        w0.x = o[0] + bsc[0]; w0.y = o[1] + bsc[1];
        w0.z = o[2] + bsc[2]; w0.w = o[3] + bsc[3];
        w1.x = o[4] + bsc[4]; w1.y = o[5] + bsc[5];
        w1.z = o[6] + bsc[6]; w1.w = o[7] + bsc[7];
        *(float4*)&g_xg[m * G3 + nt * GN + tx * 8]     = w0;
        *(float4*)&g_xg[m * G3 + nt * GN + tx * 8 + 4] = w1;
    }
}

// ---------------- kernel 3: serial GRU recurrence (dataflow, tagged 8B words) ----------------
__global__ void __launch_bounds__(NTHR, 1)
k_rnn(const float* __restrict__ gc, const float* __restrict__ Whh,
      const float* __restrict__ bhh, float* __restrict__ out, int out_size) {
    int tid  = threadIdx.x;
    int lane = tid & 31;
    int warp = tid >> 5;          // 0..3
    int cta  = blockIdx.x;        // 0..95

    __shared__ __align__(16) float hs[2][Hh];   // double buffer: one barrier per step
    __shared__ int sL[BSs];
    if (tid < BSs) sL[tid] = g_L[tid];

    int e   = lane & 1;                          // which of this warp's 2 elements I finalize
    int j_e = cta * 8 + warp * 2 + e;            // my h element (for lanes 0/1)

    // --- stationary W_hh slice in registers: [elem][gate][k] packed f32x2 ---
    ull w[2][3][12];
#pragma unroll
    for (int ee = 0; ee < 2; ee++) {
        int j = cta * 8 + warp * 2 + ee;
#pragma unroll
        for (int g = 0; g < 3; g++) {
            const float* wr = Whh + (size_t)(g * Hh + j) * Hh + 2 * lane;
#pragma unroll
            for (int k = 0; k < 12; k++)
                w[ee][g][k] = *(const ull*)(wr + 64 * k);
        }
    }

    float bh0 = __ldg(&bhh[j_e]);
    float bh1 = __ldg(&bhh[Hh + j_e]);
    float bh2 = __ldg(&bhh[2 * Hh + j_e]);
    float h_cur = __ldg(&gc[j_e]);

    __syncthreads();

    int pbase = tid * 6;   // 6 tagged elements polled by this thread
    int s = 0;             // global serial step counter (== tag)

    for (int b = 0; b < BSs; b++) {
        int Lb = sL[b];
        const float* xgb = g_xg + (size_t)b * Tt * G3;
        for (int t = 0; t < Lb; t++) {
            // prefetch this step's xg for my element (overlaps the poll)
            float xr = 0.f, xz = 0.f, xn = 0.f;
            if (lane < 2) {
                const float* x = xgb + (size_t)t * G3 + j_e;
                xr = __ldg(x);
                xz = __ldg(x + Hh);
                xn = __ldg(x + 2 * Hh);
            }

            float* hsp = hs[s & 1];
            // ---- poll tagged h words (sync + data in one 8B L2 round trip) ----
            const ull* hb = g_hb[s & 1];
            ull thi = ((ull)(unsigned int)s) << 32;
            bool d0 = false, d1 = false, d2 = false;
            while (!(d0 && d1 && d2)) {
                ull va, vb;
                if (!d0) {
                    ldcv2(hb + pbase, va, vb);
                    if (((va ^ thi) >> 32 | (vb ^ thi) >> 32) == 0) {
                        hsp[pbase]     = __uint_as_float((unsigned int)va);
                        hsp[pbase + 1] = __uint_as_float((unsigned int)vb);
                        d0 = true;
                    }
                }
                if (!d1) {
                    ldcv2(hb + pbase + 2, va, vb);
                    if (((va ^ thi) >> 32 | (vb ^ thi) >> 32) == 0) {
                        hsp[pbase + 2] = __uint_as_float((unsigned int)va);
                        hsp[pbase + 3] = __uint_as_float((unsigned int)vb);
                        d1 = true;
                    }
                }
                if (!d2) {
                    ldcv2(hb + pbase + 4, va, vb);
                    if (((va ^ thi) >> 32 | (vb ^ thi) >> 32) == 0) {
                        hsp[pbase + 4] = __uint_as_float((unsigned int)va);
                        hsp[pbase + 5] = __uint_as_float((unsigned int)vb);
                        d2 = true;
                    }
                }
            }
            __syncthreads();   // hs[s&1] fully staged

            // ---- 6 dot products (f32x2 FMAs, W stationary in registers) ----
            ull acc[2][3];
#pragma unroll
            for (int ee = 0; ee < 2; ee++)
#pragma unroll
                for (int g = 0; g < 3; g++) acc[ee][g] = 0ull;

            const ull* hp = (const ull*)hsp + lane;
#pragma unroll
            for (int k = 0; k < 12; k++) {
                ull hv = hp[32 * k];
#pragma unroll
                for (int ee = 0; ee < 2; ee++)
#pragma unroll
                    for (int g = 0; g < 3; g++) fma2(acc[ee][g], w[ee][g][k], hv);
            }

            float sum[2][3];
#pragma unroll
            for (int ee = 0; ee < 2; ee++)
#pragma unroll
                for (int g = 0; g < 3; g++) {
                    float lo, hi;
                    unpack2(acc[ee][g], lo, hi);
                    float x = lo + hi;
#pragma unroll
                    for (int o = 16; o; o >>= 1)
                        x += __shfl_xor_sync(0xFFFFFFFFu, x, o);
                    sum[ee][g] = x;
                }

            // ---- gates + publish h_new (lanes 0 and 1 each own one element) ----
            float hg_r = (e ? sum[1][0] : sum[0][0]) + bh0;
            float hg_z = (e ? sum[1][1] : sum[0][1]) + bh1;
            float hg_n = (e ? sum[1][2] : sum[0][2]) + bh2;
            if (lane < 2) {
                float r  = sigf(xr + hg_r);
                float z  = sigf(xz + hg_z);
                float n  = tanh_fast(xn + r * hg_n);
                float hn = fmaf(z, h_cur - n, n);   // (1-z)*n + z*h
                h_cur = hn;
                ull pv = (((ull)(unsigned int)(s + 1)) << 32) |
                         (ull)__float_as_uint(hn);
                __stcg(&g_hb[(s + 1) & 1][j_e], pv);
            }
            s++;
            // no second barrier: hs double buffer + the publish-order argument
            // (a CTA reaches buffer reuse only after two cross-CTA publish rounds)
        }
        if (lane < 2) out[b * Hh + j_e] = h_cur;   // per-sample final hidden state
    }
    if (lane < 2 && out_size >= BSs * Hh + Hh)
        out[BSs * Hh + j_e] = h_cur;               // detached final context hF
}

// ---------------- launch ----------------
extern "C" void kernel_launch(void* const* d_in, const int* in_sizes, int n_in,
                              void* d_out, int out_size) {
    const float* emb  = (const float*)d_in[0];
    const int*   mask = (const int*)d_in[1];   // int64 in source -> int32 under JAX default
    const float* gc   = (const float*)d_in[2];
    const float* Wih  = (const float*)d_in[3];
    const float* Whh  = (const float*)d_in[4];
    const float* bih  = (const float*)d_in[5];
    const float* bhh  = (const float*)d_in[6];
    float* out = (float*)d_out;

    k_prep<<<BSs + 1, 256>>>(mask, gc);
    dim3 gg(G3 / GN, (BSs * Tt) / GM);
    k_gemm<<<gg, 256>>>(emb, Wih, bih);
    k_rnn<<<NCTA, NTHR>>>(gc, Whh, bhh, out, out_size);
}